// round 16
// baseline (speedup 1.0000x reference)
#include <cuda_runtime.h>
#include <cuda_fp16.h>
#include <cstdint>

#define BB   1024
#define CC   256
#define HH   16
#define WW   24
#define HWL  384
#define NOBJ 10
#define DD   256
#define G2   2

// Scratch (device globals)
__device__ __half g_fusedh[(size_t)BB * HWL * CC];   // [B][HW][C] fp16
__device__ float  g_scores[(size_t)BB * NOBJ * HWL]; // [B][N][HW]
__device__ float  g_valsT[(size_t)BB * 256 * 12];    // [B][C][12] transposed vals
__device__ __half g_whp[8 * 256 * 32];               // [ks][d][32c] packed fp16 conv weights

// ---------------- helpers ----------------
__device__ __forceinline__ void cp_async16(void* smem, const void* g) {
    unsigned s = (unsigned)__cvta_generic_to_shared(smem);
    asm volatile("cp.async.cg.shared.global [%0], [%1], 16;\n" :: "r"(s), "l"(g));
}
__device__ __forceinline__ void cp_commit() { asm volatile("cp.async.commit_group;\n" ::: "memory"); }
__device__ __forceinline__ void cp_wait0()  { asm volatile("cp.async.wait_group 0;\n" ::: "memory"); }
__device__ __forceinline__ void cp_wait1()  { asm volatile("cp.async.wait_group 1;\n" ::: "memory"); }

__device__ __forceinline__ void ldsm_x4(uint32_t* r, uint32_t addr) {
    asm volatile("ldmatrix.sync.aligned.m8n8.x4.shared.b16 {%0,%1,%2,%3}, [%4];"
                 : "=r"(r[0]), "=r"(r[1]), "=r"(r[2]), "=r"(r[3]) : "r"(addr));
}
__device__ __forceinline__ void ldsm_x4_t(uint32_t* r, uint32_t addr) {
    asm volatile("ldmatrix.sync.aligned.m8n8.x4.trans.shared.b16 {%0,%1,%2,%3}, [%4];"
                 : "=r"(r[0]), "=r"(r[1]), "=r"(r[2]), "=r"(r[3]) : "r"(addr));
}
__device__ __forceinline__ void mma_f16(float* c, const uint32_t* a, uint32_t b0, uint32_t b1) {
    asm volatile("mma.sync.aligned.m16n8k16.row.col.f32.f16.f16.f32 "
                 "{%0,%1,%2,%3}, {%4,%5,%6,%7}, {%8,%9}, {%0,%1,%2,%3};"
                 : "+f"(c[0]), "+f"(c[1]), "+f"(c[2]), "+f"(c[3])
                 : "r"(a[0]), "r"(a[1]), "r"(a[2]), "r"(a[3]), "r"(b0), "r"(b1));
}

#define FFMA2(acc, v, w2) \
    asm volatile("fma.rn.f32x2 %0, %1, %2, %0;" : "+l"(acc) : "l"(v), "l"(w2))
#define UNPK2(lo, hi, v) \
    asm("mov.b64 {%0,%1}, %2;" : "=f"(lo), "=f"(hi) : "l"(v))
#define PACK_DUP(w2, w) \
    asm("mov.b64 %0, {%1, %1};" : "=l"(w2) : "f"(w))

// ---------------- k1 v2 smem layout (bytes) ----------------
// A dbl buf: ABUF(buf)=buf*20480 (256 x 80B). B dbl buf: 40960 + buf*8704 (32 x 272B)
// Epilogue reuse: FS [64][260] f32 @0 (66560), SC @66560 (8*64*10*4 = 20480)
// Persistent: QT @87040 (12288), CW @99328 (3072)
#define ABUF(buf) ((unsigned)(buf) * 20480u)
#define BBUF(buf) (40960u + (unsigned)(buf) * 8704u)
#define OFF_FS   0u
#define OFF_SC   66560u
#define OFF_QT   87040u
#define OFF_CW   99328u
#define SMEM_K1  102400u
#define FS_STRIDE 260

// =====================================================================
// k0: pack conv_w[0:256] -> fp16 [ks][d][32c]
// =====================================================================
__global__ void k0_wprep(const float* __restrict__ conv_w) {
    int idx = blockIdx.x * 256 + threadIdx.x;   // 65536
    int d = idx >> 8, c = idx & 255;
    int ks = c >> 5, cc = c & 31;
    g_whp[((ks * 256) + d) * 32 + cc] = __float2half_rn(conv_w[(size_t)c * 256 + d]);
}

// =====================================================================
// K1 v2: fp16 mma.sync GEMM D[d=256][hw=128], 512 threads (16 warps 4m x 4n).
// grid (3, 1024). A staged once per 128 hw (halved vs n=64).
// =====================================================================
__global__ __launch_bounds__(512, 1)
void k1_conv_scores(const float* __restrict__ input,
                    const float* __restrict__ conv_w,
                    const float* __restrict__ conv_b,
                    const float* __restrict__ query) {
    extern __shared__ __align__(16) char sm[];
    const int tid  = threadIdx.x;
    const int lane = tid & 31;
    const int wid  = tid >> 5;
    const int wm   = wid >> 2;           // 0..3 -> d rows wm*64
    const int wn   = wid & 3;            // 0..3 -> hw cols wn*32
    const int b    = blockIdx.y;
    const int hw0  = blockIdx.x * 128;
    const uint32_t smb = (uint32_t)__cvta_generic_to_shared(sm);

    float* qt = (float*)(sm + OFF_QT);
    float* cw = (float*)(sm + OFF_CW);
    if (tid < 256) {
        int d = tid;
#pragma unroll
        for (int n = 0; n < NOBJ; n++) qt[d * 12 + n] = query[n * 256 + d];
        qt[d * 12 + 10] = 0.f; qt[d * 12 + 11] = 0.f;
        cw[d]       = conv_w[256 * 256 + d];
        cw[256 + d] = conv_w[257 * 256 + d];
        cw[512 + d] = conv_b[d];
    }

    float acc[16][4];
#pragma unroll
    for (int i = 0; i < 16; i++)
#pragma unroll
        for (int j = 0; j < 4; j++) acc[i][j] = 0.f;

    const int bc = tid >> 4;             // c row of B tile (0..31)
    const int bh = (tid & 15) * 8;       // hw chunk (0..120)
    const float* Bg = input + (size_t)b * (CC * HWL) + hw0 + bh;

    // preamble: A(0) cp.async, B(0) LDG
    {
        const char* src = (const char*)g_whp;
#pragma unroll
        for (int j = 0; j < 2; j++) {
            int i = tid + 512 * j;
            cp_async16(sm + ABUF(0) + (unsigned)(i >> 2) * 80 + (unsigned)(i & 3) * 16,
                       src + (size_t)i * 16);
        }
        cp_commit();
    }
    float bx[8];
    {
        const float* bp = Bg + (size_t)bc * HWL;
        float4 x0 = *(const float4*)bp;
        float4 x1 = *(const float4*)(bp + 4);
        bx[0]=x0.x; bx[1]=x0.y; bx[2]=x0.z; bx[3]=x0.w;
        bx[4]=x1.x; bx[5]=x1.y; bx[6]=x1.z; bx[7]=x1.w;
    }

#pragma unroll 1
    for (int ks = 0; ks < 8; ks++) {
        const int buf = ks & 1;

        // ---- cvt + STS B(ks) ----
        {
            __half2 h0 = __floats2half2_rn(bx[0], bx[1]);
            __half2 h1 = __floats2half2_rn(bx[2], bx[3]);
            __half2 h2 = __floats2half2_rn(bx[4], bx[5]);
            __half2 h3 = __floats2half2_rn(bx[6], bx[7]);
            *(uint4*)(sm + BBUF(buf) + bc * 272 + bh * 2) =
                make_uint4(*(unsigned*)&h0, *(unsigned*)&h1, *(unsigned*)&h2, *(unsigned*)&h3);
        }

        // ---- prefetch A(ks+1) + B(ks+1) ----
        float bn[8];
        if (ks < 7) {
            const char* src = (const char*)g_whp + (size_t)(ks + 1) * 16384;
#pragma unroll
            for (int j = 0; j < 2; j++) {
                int i = tid + 512 * j;
                cp_async16(sm + ABUF(buf ^ 1) + (unsigned)(i >> 2) * 80 + (unsigned)(i & 3) * 16,
                           src + (size_t)i * 16);
            }
            cp_commit();
            const float* bp = Bg + (size_t)((ks + 1) * 32 + bc) * HWL;
            float4 x0 = *(const float4*)bp;
            float4 x1 = *(const float4*)(bp + 4);
            bn[0]=x0.x; bn[1]=x0.y; bn[2]=x0.z; bn[3]=x0.w;
            bn[4]=x1.x; bn[5]=x1.y; bn[6]=x1.z; bn[7]=x1.w;
        }

        if (ks < 7) cp_wait1(); else cp_wait0();
        __syncthreads();

        // ---- MMA ----
        const unsigned oA = ABUF(buf), oB = BBUF(buf);
#pragma unroll
        for (int s = 0; s < 2; s++) {
            const uint32_t arow = (uint32_t)(wm * 64 + (lane & 15)) * 80 + s * 32 + (lane >> 4) * 16;
            const uint32_t brow = (uint32_t)(s * 16 + (lane & 15)) * 272 + (wn * 32 + (lane >> 4) * 8) * 2;

            uint32_t ah[4][4], bf[2][4];
#pragma unroll
            for (int mi = 0; mi < 4; mi++) ldsm_x4(ah[mi], smb + oA + arow + mi * 16 * 80);
#pragma unroll
            for (int h = 0; h < 2; h++) ldsm_x4_t(bf[h], smb + oB + brow + h * 32);
#pragma unroll
            for (int mi = 0; mi < 4; mi++)
#pragma unroll
                for (int ni = 0; ni < 4; ni++)
                    mma_f16(acc[mi * 4 + ni], ah[mi],
                            bf[ni >> 1][(ni & 1) * 2], bf[ni >> 1][(ni & 1) * 2 + 1]);
        }
        __syncthreads();

#pragma unroll
        for (int p = 0; p < 8; p++) bx[p] = bn[p];
    }

    // ---- Epilogue: two 64-hw halves reusing FS ----
    float* fs = (float*)(sm + OFF_FS);
#pragma unroll 1
    for (int h = 0; h < 2; h++) {
        if ((wn >> 1) == h) {
#pragma unroll
            for (int mi = 0; mi < 4; mi++)
#pragma unroll
                for (int ni = 0; ni < 4; ni++) {
                    const float* a = acc[mi * 4 + ni];
                    int d0  = wm * 64 + mi * 16 + (lane >> 2);
                    int hwv = (wn & 1) * 32 + ni * 8 + (lane & 3) * 2;
                    fs[hwv * FS_STRIDE + d0]           = a[0];
                    fs[(hwv + 1) * FS_STRIDE + d0]     = a[1];
                    fs[hwv * FS_STRIDE + d0 + 8]       = a[2];
                    fs[(hwv + 1) * FS_STRIDE + d0 + 8] = a[3];
                }
        }
        __syncthreads();

        // coords + bias + relu + score partials (512 thr: hwl=tid&63, q=tid>>6 over 8x32 d)
        {
            const int hwl = tid & 63;
            const int q   = tid >> 6;
            const int hw  = hw0 + h * 64 + hwl;
            const float xc = (float)(hw % WW) * (1.0f / (WW - 1));
            const float yc = (float)(hw / WW) * (1.0f / (HH - 1));
            float s[NOBJ];
#pragma unroll
            for (int n = 0; n < NOBJ; n++) s[n] = 0.f;

            float* row = fs + hwl * FS_STRIDE + q * 32;
#pragma unroll
            for (int j4 = 0; j4 < 8; j4++) {
                float4 v = *(float4*)(row + j4 * 4);
                float vv[4] = {v.x, v.y, v.z, v.w};
#pragma unroll
                for (int e = 0; e < 4; e++) {
                    int d = q * 32 + j4 * 4 + e;
                    float f = vv[e] + xc * cw[d] + yc * cw[256 + d] + cw[512 + d];
                    f = fmaxf(f, 0.f);
                    vv[e] = f;
                    float4 q0 = *(const float4*)(qt + d * 12);
                    float4 q1 = *(const float4*)(qt + d * 12 + 4);
                    float4 q2 = *(const float4*)(qt + d * 12 + 8);
                    s[0] = fmaf(q0.x, f, s[0]); s[1] = fmaf(q0.y, f, s[1]);
                    s[2] = fmaf(q0.z, f, s[2]); s[3] = fmaf(q0.w, f, s[3]);
                    s[4] = fmaf(q1.x, f, s[4]); s[5] = fmaf(q1.y, f, s[5]);
                    s[6] = fmaf(q1.z, f, s[6]); s[7] = fmaf(q1.w, f, s[7]);
                    s[8] = fmaf(q2.x, f, s[8]); s[9] = fmaf(q2.y, f, s[9]);
                }
                *(float4*)(row + j4 * 4) = make_float4(vv[0], vv[1], vv[2], vv[3]);
            }
            float* scp = (float*)(sm + OFF_SC);
#pragma unroll
            for (int n = 0; n < NOBJ; n++) scp[q * 640 + hwl * 10 + n] = s[n];
        }
        __syncthreads();

        if (tid < 64) {
            float* scp = (float*)(sm + OFF_SC);
#pragma unroll
            for (int n = 0; n < NOBJ; n++) {
                float v = 0.f;
#pragma unroll
                for (int q = 0; q < 8; q++) v += scp[q * 640 + tid * 10 + n];
                g_scores[((size_t)b * NOBJ + n) * HWL + hw0 + h * 64 + tid] = v;
            }
        }

        // fused store fp16 (512 thr: dchunk=tid&63, hwb=tid>>6, 8 rows each)
        {
            const int dchunk = tid & 63;
            const int hwb    = tid >> 6;
#pragma unroll
            for (int it = 0; it < 8; it++) {
                int hwr = hwb + it * 8;
                float4 v = *(float4*)(fs + hwr * FS_STRIDE + dchunk * 4);
                __half2 h0 = __floats2half2_rn(v.x, v.y);
                __half2 h1 = __floats2half2_rn(v.z, v.w);
                *(uint2*)(g_fusedh + ((size_t)b * HWL + hw0 + h * 64 + hwr) * 256 + dchunk * 4) =
                    make_uint2(*(unsigned*)&h0, *(unsigned*)&h1);
            }
        }
        __syncthreads();
    }
}

// =====================================================================
// K2a: softmax + vals -> g_valsT[b][c][12]. grid (2, 1024), 256 thr. (frozen)
// =====================================================================
__global__ __launch_bounds__(256)
void k2a_vals() {
    __shared__ __align__(16) float attn_t[HWL][12];
    __shared__ float2 part_s[4][NOBJ][64];

    const int chalf = blockIdx.x;
    const int b     = blockIdx.y;
    const int tid   = threadIdx.x;
    const int lane  = tid & 31;
    const int wid   = tid >> 5;
    const int c2l   = tid & 63;
    const int hq    = tid >> 6;

    for (int n = wid; n < NOBJ; n += 8) {
        const float* sc = g_scores + ((size_t)b * NOBJ + n) * HWL;
        float v[12];
        float mx = -1e30f;
#pragma unroll
        for (int r = 0; r < 12; r++) { v[r] = sc[lane + 32 * r]; mx = fmaxf(mx, v[r]); }
#pragma unroll
        for (int o = 16; o > 0; o >>= 1) mx = fmaxf(mx, __shfl_xor_sync(0xffffffffu, mx, o));
        float ssum = 0.f;
#pragma unroll
        for (int r = 0; r < 12; r++) { v[r] = __expf(v[r] - mx); ssum += v[r]; }
#pragma unroll
        for (int o = 16; o > 0; o >>= 1) ssum += __shfl_xor_sync(0xffffffffu, ssum, o);
        const float inv = 1.f / ssum;
#pragma unroll
        for (int r = 0; r < 12; r++) attn_t[lane + 32 * r][n] = v[r] * inv;
    }
    __syncthreads();

    float2 av[NOBJ];
#pragma unroll
    for (int n = 0; n < NOBJ; n++) av[n] = make_float2(0.f, 0.f);

    const __half2* fb = (const __half2*)g_fusedh + (size_t)b * (HWL * 128) + chalf * 64 + c2l;
    const int hwbeg = hq * 96;
#pragma unroll 1
    for (int hw8 = hwbeg; hw8 < hwbeg + 96; hw8 += 8) {
        __half2 hv[8];
#pragma unroll
        for (int r = 0; r < 8; r++) hv[r] = fb[(size_t)(hw8 + r) * 128];
#pragma unroll
        for (int r = 0; r < 8; r++) {
            float2 f = __half22float2(hv[r]);
            int hw = hw8 + r;
            float4 a0 = *(const float4*)&attn_t[hw][0];
            float4 a1 = *(const float4*)&attn_t[hw][4];
            float4 a2 = *(const float4*)&attn_t[hw][8];
            av[0].x = fmaf(a0.x, f.x, av[0].x); av[0].y = fmaf(a0.x, f.y, av[0].y);
            av[1].x = fmaf(a0.y, f.x, av[1].x); av[1].y = fmaf(a0.y, f.y, av[1].y);
            av[2].x = fmaf(a0.z, f.x, av[2].x); av[2].y = fmaf(a0.z, f.y, av[2].y);
            av[3].x = fmaf(a0.w, f.x, av[3].x); av[3].y = fmaf(a0.w, f.y, av[3].y);
            av[4].x = fmaf(a1.x, f.x, av[4].x); av[4].y = fmaf(a1.x, f.y, av[4].y);
            av[5].x = fmaf(a1.y, f.x, av[5].x); av[5].y = fmaf(a1.y, f.y, av[5].y);
            av[6].x = fmaf(a1.z, f.x, av[6].x); av[6].y = fmaf(a1.z, f.y, av[6].y);
            av[7].x = fmaf(a1.w, f.x, av[7].x); av[7].y = fmaf(a1.w, f.y, av[7].y);
            av[8].x = fmaf(a2.x, f.x, av[8].x); av[8].y = fmaf(a2.x, f.y, av[8].y);
            av[9].x = fmaf(a2.y, f.x, av[9].x); av[9].y = fmaf(a2.y, f.y, av[9].y);
        }
    }
#pragma unroll
    for (int n = 0; n < NOBJ; n++) part_s[hq][n][c2l] = av[n];
    __syncthreads();

    if (tid < 64) {
        float vx[12], vy[12];
#pragma unroll
        for (int n = 0; n < NOBJ; n++) {
            float2 p0 = part_s[0][n][tid];
            float2 p1 = part_s[1][n][tid];
            float2 p2 = part_s[2][n][tid];
            float2 p3 = part_s[3][n][tid];
            vx[n] = p0.x + p1.x + p2.x + p3.x;
            vy[n] = p0.y + p1.y + p2.y + p3.y;
        }
        vx[10] = vx[11] = vy[10] = vy[11] = 0.f;
        float* r0 = g_valsT + ((size_t)b * 256 + chalf * 128 + 2 * tid) * 12;
        *(float4*)(r0)      = make_float4(vx[0], vx[1], vx[2], vx[3]);
        *(float4*)(r0 + 4)  = make_float4(vx[4], vx[5], vx[6], vx[7]);
        *(float4*)(r0 + 8)  = make_float4(vx[8], vx[9], 0.f, 0.f);
        *(float4*)(r0 + 12) = make_float4(vy[0], vy[1], vy[2], vy[3]);
        *(float4*)(r0 + 16) = make_float4(vy[4], vy[5], vy[6], vy[7]);
        *(float4*)(r0 + 20) = make_float4(vy[8], vy[9], 0.f, 0.f);
    }
}

// =====================================================================
// K2b (round-14 fp32-weight version): FFMA2 GEMMs, thread = (dpair, g).
// grid 512 (G2 batches/CTA), 256 threads, 3 CTAs/SM.
// smem: vt [2][256][12] f32 @0 (24576) | ws 2x16KB @24576 | red @57344
// =====================================================================
#define K2B_VT   0u
#define K2B_WS(buf) (24576u + (unsigned)(buf) * 16384u)
#define K2B_RED  57344u
#define SMEM_K2B 57472u

__device__ __forceinline__ void k2b_gemm(const float* __restrict__ W,
                                         char* sm2, uint32_t smb,
                                         uint64_t acc2[10], int tid,
                                         int dp, int g) {
#pragma unroll
    for (int i = 0; i < 10; i++) acc2[i] = 0;

#pragma unroll
    for (int j = 0; j < 4; j++) {
        int i = tid + 256 * j;
        cp_async16(sm2 + K2B_WS(0) + (unsigned)i * 16, (const char*)W + (size_t)i * 16);
    }
    cp_commit();

    const uint32_t vbase = smb + K2B_VT + (unsigned)g * 12288u;

#pragma unroll 1
    for (int kt = 0; kt < 16; kt++) {
        const int buf = kt & 1;
        if (kt < 15) {
            const char* srcW = (const char*)W + (size_t)(kt + 1) * 16384;
#pragma unroll
            for (int j = 0; j < 4; j++) {
                int i = tid + 256 * j;
                cp_async16(sm2 + K2B_WS(buf ^ 1) + (unsigned)i * 16, srcW + (size_t)i * 16);
            }
            cp_commit();
            cp_wait1();
        } else {
            cp_wait0();
        }
        __syncthreads();

        const uint32_t wsb = smb + K2B_WS(buf) + (unsigned)dp * 8u;
        const uint32_t va  = vbase + (unsigned)(kt * 16) * 48u;
#pragma unroll
        for (int kk = 0; kk < 16; kk++) {
            uint64_t wv;
            asm volatile("ld.shared.u64 %0, [%1];" : "=l"(wv) : "r"(wsb + (unsigned)kk * 1024u));
            float w0, w1;
            UNPK2(w0, w1, wv);
            uint64_t w20, w21;
            PACK_DUP(w20, w0);
            PACK_DUP(w21, w1);
            uint32_t a = va + (unsigned)kk * 48u;
            uint64_t v0, v1, v2, v3, v4;
            asm volatile("ld.shared.v2.u64 {%0,%1}, [%2];" : "=l"(v0), "=l"(v1) : "r"(a));
            asm volatile("ld.shared.v2.u64 {%0,%1}, [%2];" : "=l"(v2), "=l"(v3) : "r"(a + 16));
            asm volatile("ld.shared.u64 %0, [%1];"         : "=l"(v4)           : "r"(a + 32));
            FFMA2(acc2[0], v0, w20); FFMA2(acc2[5], v0, w21);
            FFMA2(acc2[1], v1, w20); FFMA2(acc2[6], v1, w21);
            FFMA2(acc2[2], v2, w20); FFMA2(acc2[7], v2, w21);
            FFMA2(acc2[3], v3, w20); FFMA2(acc2[8], v3, w21);
            FFMA2(acc2[4], v4, w20); FFMA2(acc2[9], v4, w21);
        }
        __syncthreads();
    }
}

__global__ __launch_bounds__(256, 3)
void k2b_rest(const float* __restrict__ feat_w, const float* __restrict__ feat_b,
              const float* __restrict__ o1w, const float* __restrict__ o1b,
              const float* __restrict__ o2w, const float* __restrict__ o2b,
              const int* __restrict__ olen_raw, float* __restrict__ out) {
    extern __shared__ __align__(16) char sm2[];
    float* vt  = (float*)(sm2 + K2B_VT);
    float* red = (float*)(sm2 + K2B_RED);
    const uint32_t smb = (uint32_t)__cvta_generic_to_shared(sm2);

    const int tid  = threadIdx.x;
    const int lane = tid & 31;
    const int dp   = tid & 127;
    const int g    = tid >> 7;
    const int d0   = 2 * dp;
    const int bs   = blockIdx.x * G2;
    const int b    = bs + g;

    if (tid < G2 * NOBJ) red[tid] = 0.f;

    {
        const float4* src = (const float4*)(g_valsT + (size_t)bs * 3072);
        float4* dst = (float4*)vt;
#pragma unroll
        for (int i = tid; i < G2 * 768; i += 256) dst[i] = src[i];
    }
    __syncthreads();

    int Lg;
    {
        const int* pi = olen_raw;
        bool w64 = (pi[1] == 0 && pi[3] == 0);
        Lg = w64 ? pi[2 * b] : pi[b];
    }

    uint64_t acc2[10];

    // ---- reps ----
    k2b_gemm(feat_w, sm2, smb, acc2, tid, dp, g);
    float rp[2][NOBJ];
    {
        const float fb0 = feat_b[d0], fb1 = feat_b[d0 + 1];
#pragma unroll
        for (int p = 0; p < 5; p++) {
            float lo, hi;
            UNPK2(lo, hi, acc2[p]);
            rp[0][2 * p]     = fmaxf(lo + fb0, 0.f);
            rp[0][2 * p + 1] = fmaxf(hi + fb0, 0.f);
            UNPK2(lo, hi, acc2[5 + p]);
            rp[1][2 * p]     = fmaxf(lo + fb1, 0.f);
            rp[1][2 * p + 1] = fmaxf(hi + fb1, 0.f);
        }
#pragma unroll
        for (int n = 0; n < NOBJ; n++) {
            float sq = rp[0][n] * rp[0][n] + rp[1][n] * rp[1][n];
#pragma unroll
            for (int o = 16; o > 0; o >>= 1) sq += __shfl_xor_sync(0xffffffffu, sq, o);
            if (lane == 0) atomicAdd(&red[g * NOBJ + n], sq);
        }
    }
    __syncthreads();
    {
        float inv[NOBJ];
#pragma unroll
        for (int n = 0; n < NOBJ; n++)
            inv[n] = (n < Lg) ? (1.f / fmaxf(sqrtf(red[g * NOBJ + n]), 1e-12f)) : 0.f;
        float* row0 = vt + (g * 256 + d0) * 12;
        float* row1 = vt + (g * 256 + d0 + 1) * 12;
#pragma unroll
        for (int n = 0; n < NOBJ; n++) {
            float r0 = rp[0][n] * inv[n];
            float r1 = rp[1][n] * inv[n];
            row0[n] = r0; row1[n] = r1;
            *(float2*)(out + ((size_t)b * NOBJ + n) * 256 + d0) = make_float2(r0, r1);
        }
        row0[10] = 0.f; row0[11] = 0.f;
        row1[10] = 0.f; row1[11] = 0.f;
    }
    __syncthreads();

    // ---- o2 (regs) ----
    k2b_gemm(o2w, sm2, smb, acc2, tid, dp, g);
    float o2s[2][NOBJ];
    {
        const float b20 = o2b[d0], b21 = o2b[d0 + 1];
#pragma unroll
        for (int p = 0; p < 5; p++) {
            float lo, hi;
            UNPK2(lo, hi, acc2[p]);
            o2s[0][2 * p] = lo + b20; o2s[0][2 * p + 1] = hi + b20;
            UNPK2(lo, hi, acc2[5 + p]);
            o2s[1][2 * p] = lo + b21; o2s[1][2 * p + 1] = hi + b21;
        }
    }
    __syncthreads();

    // ---- o1 ----
    k2b_gemm(o1w, sm2, smb, acc2, tid, dp, g);

    // ---- pair ----
    {
        const float b10 = o1b[d0], b11 = o1b[d0 + 1];
        float* pout = out + (size_t)BB * NOBJ * 256
                    + ((size_t)b * NOBJ * NOBJ) * 256 + d0;
#pragma unroll 1
        for (int i = 0; i < NOBJ; i++) {
            const int p = i >> 1, hs = i & 1;
            float a1lo, a1hi;
            UNPK2(a1lo, a1hi, acc2[p]);
            float a1_d0 = (hs ? a1hi : a1lo) + b10;
            UNPK2(a1lo, a1hi, acc2[5 + p]);
            float a1_d1 = (hs ? a1hi : a1lo) + b11;
            const bool mi = (i < Lg);
#pragma unroll
            for (int j = 0; j < NOBJ; j++) {
                const bool mm = mi && (j < Lg);
                float2 v;
                v.x = mm ? (a1_d0 + o2s[0][j]) : 0.f;
                v.y = mm ? (a1_d1 + o2s[1][j]) : 0.f;
                *(float2*)(pout + (size_t)(i * NOBJ + j) * 256) = v;
            }
        }
    }
}

// Spacers: position k1 as the 4th kernel launch (ncu capture slot).
__global__ void k_spacer() {}

// =====================================================================
extern "C" void kernel_launch(void* const* d_in, const int* in_sizes, int n_in,
                              void* d_out, int out_size) {
    const float* input  = (const float*)d_in[0];
    const int*   olen   = (const int*)d_in[2];
    const float* query  = (const float*)d_in[3];
    const float* conv_w = (const float*)d_in[4];
    const float* conv_b = (const float*)d_in[5];
    const float* feat_w = (const float*)d_in[6];
    const float* feat_b = (const float*)d_in[7];
    const float* o1w    = (const float*)d_in[8];
    const float* o1b    = (const float*)d_in[9];
    const float* o2w    = (const float*)d_in[10];
    const float* o2b    = (const float*)d_in[11];
    float* out = (float*)d_out;

    cudaFuncSetAttribute(k1_conv_scores, cudaFuncAttributeMaxDynamicSharedMemorySize, SMEM_K1);
    cudaFuncSetAttribute(k2b_rest, cudaFuncAttributeMaxDynamicSharedMemorySize, SMEM_K2B);

    k0_wprep<<<256, 256>>>(conv_w);
    k_spacer<<<1, 1>>>();
    k_spacer<<<1, 1>>>();
    dim3 g1(HWL / 128, BB);
    k1_conv_scores<<<g1, 512, SMEM_K1>>>(input, conv_w, conv_b, query);
    k2a_vals<<<dim3(2, BB), 256>>>();
    k2b_rest<<<BB / G2, 256, SMEM_K2B>>>(feat_w, feat_b, o1w, o1b, o2w, o2b, olen, out);
}